// round 1
// baseline (speedup 1.0000x reference)
#include <cuda_runtime.h>

// DistMap: d[b,i,j] = sum_c (a[b,c,i] - b[b,c,j])^2
//        = aa[b,i] + bb[b,j] - 2 * sum_c a[b,c,i]*b[b,c,j]
// a: [B, C, N] fp32, b: [B, C, M] fp32, out: [B, N, M] fp32
// B=4, C=64, N=M=4096.

#define C_DIM 64
#define N_DIM 4096
#define M_DIM 4096

#define BM 128
#define BN 128
#define BK 32
#define NTHREADS 256

__global__ __launch_bounds__(NTHREADS, 2)
void distmap_kernel(const float* __restrict__ A,   // [B, C, N]
                    const float* __restrict__ Bm,  // [B, C, M]
                    float* __restrict__ D)         // [B, N, M]
{
    __shared__ float As[BK][BM];
    __shared__ float Bs[BK][BN];
    __shared__ float aa_s[BM];
    __shared__ float bb_s[BN];

    const int tid = threadIdx.x;
    const int tx  = tid & 15;   // 0..15 -> output cols
    const int ty  = tid >> 4;   // 0..15 -> output rows
    const int i0  = blockIdx.y * BM;
    const int j0  = blockIdx.x * BN;
    const int b   = blockIdx.z;

    const float* Ab = A  + (size_t)b * C_DIM * N_DIM;
    const float* Bb = Bm + (size_t)b * C_DIM * M_DIM;

    float acc[8][8];
#pragma unroll
    for (int r = 0; r < 8; r++)
#pragma unroll
        for (int c = 0; c < 8; c++) acc[r][c] = 0.0f;

    // per-thread partial squared norm: threads 0..127 own aa[i_local=tid],
    // threads 128..255 own bb[j_local=tid-128]
    float norm_part = 0.0f;

    for (int kk = 0; kk < C_DIM; kk += BK) {
        // ---- load tiles: BK x 128 floats each = 1024 float4 per tile, 4 per thread
#pragma unroll
        for (int l = 0; l < 4; l++) {
            int t    = tid + l * NTHREADS;   // float4 index within tile
            int row  = t >> 5;               // 32 float4 per 128-float row
            int col4 = (t & 31) << 2;
            float4 va = *(const float4*)&Ab[(size_t)(kk + row) * N_DIM + i0 + col4];
            *(float4*)&As[row][col4] = va;
            float4 vb = *(const float4*)&Bb[(size_t)(kk + row) * M_DIM + j0 + col4];
            *(float4*)&Bs[row][col4] = vb;
        }
        __syncthreads();

        // ---- squared-norm partials from resident smem (free epilogue data)
        if (tid < BM) {
#pragma unroll
            for (int c = 0; c < BK; c++) {
                float v = As[c][tid];
                norm_part += v * v;
            }
        } else {
            int t = tid - BM;
#pragma unroll
            for (int c = 0; c < BK; c++) {
                float v = Bs[c][t];
                norm_part += v * v;
            }
        }

        // ---- main 8x8 register-blocked FMA loop
#pragma unroll 8
        for (int c = 0; c < BK; c++) {
            float4 a0 = *(const float4*)&As[c][ty * 8];
            float4 a1 = *(const float4*)&As[c][ty * 8 + 4];
            float4 b0 = *(const float4*)&Bs[c][tx * 8];
            float4 b1 = *(const float4*)&Bs[c][tx * 8 + 4];
            float ar[8] = {a0.x, a0.y, a0.z, a0.w, a1.x, a1.y, a1.z, a1.w};
            float br[8] = {b0.x, b0.y, b0.z, b0.w, b1.x, b1.y, b1.z, b1.w};
#pragma unroll
            for (int r = 0; r < 8; r++)
#pragma unroll
                for (int cc = 0; cc < 8; cc++)
                    acc[r][cc] += ar[r] * br[cc];
        }
        __syncthreads();
    }

    // ---- publish norms, then epilogue
    if (tid < BM) aa_s[tid] = norm_part;
    else          bb_s[tid - BM] = norm_part;
    __syncthreads();

    float bbr[8];
#pragma unroll
    for (int cc = 0; cc < 8; cc++) bbr[cc] = bb_s[tx * 8 + cc];

    float* Drow = D + (size_t)b * N_DIM * M_DIM + (size_t)(i0 + ty * 8) * M_DIM + j0 + tx * 8;
#pragma unroll
    for (int r = 0; r < 8; r++) {
        float aar = aa_s[ty * 8 + r];
        float4 o0, o1;
        o0.x = aar + bbr[0] - 2.0f * acc[r][0];
        o0.y = aar + bbr[1] - 2.0f * acc[r][1];
        o0.z = aar + bbr[2] - 2.0f * acc[r][2];
        o0.w = aar + bbr[3] - 2.0f * acc[r][3];
        o1.x = aar + bbr[4] - 2.0f * acc[r][4];
        o1.y = aar + bbr[5] - 2.0f * acc[r][5];
        o1.z = aar + bbr[6] - 2.0f * acc[r][6];
        o1.w = aar + bbr[7] - 2.0f * acc[r][7];
        *(float4*)&Drow[(size_t)r * M_DIM]     = o0;
        *(float4*)&Drow[(size_t)r * M_DIM + 4] = o1;
    }
}

extern "C" void kernel_launch(void* const* d_in, const int* in_sizes, int n_in,
                              void* d_out, int out_size)
{
    const float* a = (const float*)d_in[0];
    const float* b = (const float*)d_in[1];
    float* out = (float*)d_out;

    dim3 grid(M_DIM / BN, N_DIM / BM, 4);  // (32, 32, 4)
    distmap_kernel<<<grid, NTHREADS>>>(a, b, out);
}

// round 3
// speedup vs baseline: 2.1062x; 2.1062x over previous
#include <cuda_runtime.h>
#include <cstdint>

// DistMap: d[b,i,j] = aa[b,i] + bb[b,j] - 2 * sum_c a[b,c,i]*b[b,c,j]
// a: [B=4, C=64, N=4096] fp32, b: [4, 64, 4096] fp32, out: [4, 4096, 4096] fp32
// Cross term via mma.sync tf32 (m16n8k8). GEMM dims: M = i, N = j (j contiguous
// in output => coalesced stores). K = 64, fully SMEM-resident (no mainloop).

#define C_DIM 64
#define NN    4096
#define TILE  128
#define NTHREADS 256
#define LDT   132   // smem row stride in elements (128 + 4 pad -> conflict-free frags)

// ---------------- norms precompute (exact fp32) ----------------

__device__ float g_aa[4 * NN];
__device__ float g_bb[4 * NN];

__global__ void norms_kernel(const float* __restrict__ A, const float* __restrict__ B) {
    int idx = blockIdx.x * blockDim.x + threadIdx.x;    // 0..32767
    int which = idx >> 14;
    int r = idx & 16383;                                 // b*4096 + i
    const float* src = (which ? B : A) + (size_t)(r >> 12) * (C_DIM * NN) + (r & 4095);
    float s = 0.0f;
#pragma unroll
    for (int c = 0; c < C_DIM; c++) { float v = src[(size_t)c * NN]; s += v * v; }
    (which ? g_bb : g_aa)[r] = s;
}

// ---------------- helpers ----------------

__device__ __forceinline__ uint32_t f2tf32(float x) {
    uint32_t u;
    asm("cvt.rna.tf32.f32 %0, %1;" : "=r"(u) : "f"(x));
    return u;
}

__device__ __forceinline__ void mma_tf32(float c[4], const uint32_t a[4], const uint32_t b[2]) {
    asm volatile(
        "mma.sync.aligned.m16n8k8.row.col.f32.tf32.tf32.f32 "
        "{%0,%1,%2,%3}, {%4,%5,%6,%7}, {%8,%9}, {%0,%1,%2,%3};"
        : "+f"(c[0]), "+f"(c[1]), "+f"(c[2]), "+f"(c[3])
        : "r"(a[0]), "r"(a[1]), "r"(a[2]), "r"(a[3]), "r"(b[0]), "r"(b[1]));
}

// ---------------- main kernel ----------------
// SMEM: As[64][LDT] (tf32 bits of a-tile, [k][i]), Bs[64][LDT] ([k][j]),
// then aa_s[128], bb_s[128] floats.

#define SMEM_AS 0
#define SMEM_BS (64 * LDT * 4)
#define SMEM_AA (2 * 64 * LDT * 4)
#define SMEM_BB (SMEM_AA + 128 * 4)
#define SMEM_TOTAL (SMEM_BB + 128 * 4)

__global__ __launch_bounds__(NTHREADS, 2)
void distmap_mma_kernel(const float* __restrict__ A,   // [4, 64, 4096]
                        const float* __restrict__ Bm,  // [4, 64, 4096]
                        float* __restrict__ D)         // [4, 4096, 4096]
{
    extern __shared__ __align__(16) char smem[];
    uint32_t* As = (uint32_t*)(smem + SMEM_AS);
    uint32_t* Bs = (uint32_t*)(smem + SMEM_BS);
    float* aa_s  = (float*)(smem + SMEM_AA);
    float* bb_s  = (float*)(smem + SMEM_BB);

    const int tid  = threadIdx.x;
    const int lane = tid & 31;
    const int wid  = tid >> 5;
    const int gid  = lane >> 2;   // 0..7
    const int tig  = lane & 3;    // 0..3
    const int wy   = wid >> 1;    // 0..3  -> i
    const int wx   = wid & 1;     // 0..1  -> j
    const int i_w  = wy * 32;
    const int j_w  = wx * 64;

    const int b  = blockIdx.z;
    const int i0 = blockIdx.y * TILE;
    const int j0 = blockIdx.x * TILE;

    const float* Ab = A  + (size_t)b * C_DIM * NN;
    const float* Bb = Bm + (size_t)b * C_DIM * NN;

    // norms into smem
    if (tid < 128) aa_s[tid] = g_aa[b * NN + i0 + tid];
    else           bb_s[tid - 128] = g_bb[b * NN + j0 + (tid - 128)];

    // Load tiles: gmem [c][n] (n contiguous) -> smem [k=c][n], tf32-converted.
    // 2048 float4 per tile; 256 threads -> 8 iterations covering both tiles.
#pragma unroll
    for (int it = 0; it < 8; it++) {
        int t4   = tid + it * NTHREADS;      // float4 index 0..2047
        int c    = t4 >> 5;
        int col4 = (t4 & 31) << 2;
        float4 va = *(const float4*)&Ab[(size_t)c * NN + i0 + col4];
        float4 vb = *(const float4*)&Bb[(size_t)c * NN + j0 + col4];
        uint4 ua = { f2tf32(va.x), f2tf32(va.y), f2tf32(va.z), f2tf32(va.w) };
        uint4 ub = { f2tf32(vb.x), f2tf32(vb.y), f2tf32(vb.z), f2tf32(vb.w) };
        *(uint4*)&As[c * LDT + col4] = ua;
        *(uint4*)&Bs[c * LDT + col4] = ub;
    }
    __syncthreads();

    // accumulate: 2 m-tiles x 8 n-tiles of m16n8k8, over 8 k-steps
    float acc[2][8][4];
#pragma unroll
    for (int mt = 0; mt < 2; mt++)
#pragma unroll
        for (int nt = 0; nt < 8; nt++)
#pragma unroll
            for (int e = 0; e < 4; e++) acc[mt][nt][e] = 0.0f;

#pragma unroll
    for (int s = 0; s < 8; s++) {
        const int k0 = s * 8;
        uint32_t afr[2][4];
#pragma unroll
        for (int mt = 0; mt < 2; mt++) {
            int ib = i_w + mt * 16 + gid;
            afr[mt][0] = As[(k0 + tig)     * LDT + ib];
            afr[mt][1] = As[(k0 + tig)     * LDT + ib + 8];
            afr[mt][2] = As[(k0 + 4 + tig) * LDT + ib];
            afr[mt][3] = As[(k0 + 4 + tig) * LDT + ib + 8];
        }
        uint32_t bfr[8][2];
#pragma unroll
        for (int nt = 0; nt < 8; nt++) {
            int jb = j_w + nt * 8 + gid;
            bfr[nt][0] = Bs[(k0 + tig)     * LDT + jb];
            bfr[nt][1] = Bs[(k0 + 4 + tig) * LDT + jb];
        }
#pragma unroll
        for (int mt = 0; mt < 2; mt++)
#pragma unroll
            for (int nt = 0; nt < 8; nt++)
                mma_tf32(acc[mt][nt], afr[mt], bfr[nt]);
    }

    // epilogue: d = aa + bb - 2*ab, coalesced float2 stores (cols = j)
    float aav[2][2];
#pragma unroll
    for (int mt = 0; mt < 2; mt++) {
        aav[mt][0] = aa_s[i_w + mt * 16 + gid];
        aav[mt][1] = aa_s[i_w + mt * 16 + 8 + gid];
    }
    float bbv[8][2];
#pragma unroll
    for (int nt = 0; nt < 8; nt++) {
        bbv[nt][0] = bb_s[j_w + nt * 8 + 2 * tig];
        bbv[nt][1] = bb_s[j_w + nt * 8 + 2 * tig + 1];
    }

    float* Dbase = D + (size_t)b * NN * NN;
#pragma unroll
    for (int mt = 0; mt < 2; mt++) {
        int row0 = i0 + i_w + mt * 16 + gid;
#pragma unroll
        for (int nt = 0; nt < 8; nt++) {
            int col = j0 + j_w + nt * 8 + 2 * tig;
            float2 o0, o1;
            o0.x = aav[mt][0] + bbv[nt][0] - 2.0f * acc[mt][nt][0];
            o0.y = aav[mt][0] + bbv[nt][1] - 2.0f * acc[mt][nt][1];
            o1.x = aav[mt][1] + bbv[nt][0] - 2.0f * acc[mt][nt][2];
            o1.y = aav[mt][1] + bbv[nt][1] - 2.0f * acc[mt][nt][3];
            *(float2*)&Dbase[(size_t)row0 * NN + col]       = o0;
            *(float2*)&Dbase[(size_t)(row0 + 8) * NN + col] = o1;
        }
    }
}

// ---------------- launch ----------------

extern "C" void kernel_launch(void* const* d_in, const int* in_sizes, int n_in,
                              void* d_out, int out_size)
{
    const float* a = (const float*)d_in[0];
    const float* b = (const float*)d_in[1];
    float* out = (float*)d_out;

    cudaFuncSetAttribute(distmap_mma_kernel,
                         cudaFuncAttributeMaxDynamicSharedMemorySize, SMEM_TOTAL);

    norms_kernel<<<128, 256>>>(a, b);
    dim3 grid(NN / TILE, NN / TILE, 4);   // (32, 32, 4)
    distmap_mma_kernel<<<grid, NTHREADS, SMEM_TOTAL>>>(a, b, out);
}

// round 4
// speedup vs baseline: 2.3502x; 1.1158x over previous
#include <cuda_runtime.h>
#include <cstdint>

// DistMap: d[b,i,j] = aa[b,i] + bb[b,j] - 2 * sum_c a[b,c,i]*b[b,c,j]
// a: [B=4, C=64, N=4096] fp32, b: [4, 64, 4096] fp32, out: [4, 4096, 4096] fp32
// Cross term via mma.sync tf32 (m16n8k8). CTA tile 128x128, K=64 SMEM-resident.
// 4 warps, 64x64 warp tiles (A/B smem duplication x2/x2 instead of x2/x4).

#define C_DIM 64
#define NN    4096
#define TILE  128
#define NTHREADS 128
#define LDT   132   // smem row stride (128 + 4 pad): conflict-free fragment LDS

// ---------------- norms precompute (exact fp32) ----------------

__device__ float g_aa[4 * NN];
__device__ float g_bb[4 * NN];

__global__ void norms_kernel(const float* __restrict__ A, const float* __restrict__ B) {
    int idx = blockIdx.x * blockDim.x + threadIdx.x;    // 0..32767
    int which = idx >> 14;
    int r = idx & 16383;                                 // b*4096 + i
    const float* src = (which ? B : A) + (size_t)(r >> 12) * (C_DIM * NN) + (r & 4095);
    float s = 0.0f;
#pragma unroll
    for (int c = 0; c < C_DIM; c++) { float v = src[(size_t)c * NN]; s += v * v; }
    (which ? g_bb : g_aa)[r] = s;
}

// ---------------- helpers ----------------

__device__ __forceinline__ uint32_t f2tf32(float x) {
    uint32_t u;
    asm("cvt.rna.tf32.f32 %0, %1;" : "=r"(u) : "f"(x));
    return u;
}

__device__ __forceinline__ void mma_tf32(float c[4], const uint32_t a[4], const uint32_t b[2]) {
    asm volatile(
        "mma.sync.aligned.m16n8k8.row.col.f32.tf32.tf32.f32 "
        "{%0,%1,%2,%3}, {%4,%5,%6,%7}, {%8,%9}, {%0,%1,%2,%3};"
        : "+f"(c[0]), "+f"(c[1]), "+f"(c[2]), "+f"(c[3])
        : "r"(a[0]), "r"(a[1]), "r"(a[2]), "r"(a[3]), "r"(b[0]), "r"(b[1]));
}

// ---------------- main kernel ----------------
// SMEM: As[64][LDT] (tf32 bits, [k][i]), Bs[64][LDT] ([k][j]), aa_s[128], bb_s[128]

#define SMEM_AS 0
#define SMEM_BS (64 * LDT * 4)
#define SMEM_AA (2 * 64 * LDT * 4)
#define SMEM_BB (SMEM_AA + 128 * 4)
#define SMEM_TOTAL (SMEM_BB + 128 * 4)

__global__ __launch_bounds__(NTHREADS, 2)
void distmap_mma_kernel(const float* __restrict__ A,   // [4, 64, 4096]
                        const float* __restrict__ Bm,  // [4, 64, 4096]
                        float* __restrict__ D)         // [4, 4096, 4096]
{
    extern __shared__ __align__(16) char smem[];
    uint32_t* As = (uint32_t*)(smem + SMEM_AS);
    uint32_t* Bs = (uint32_t*)(smem + SMEM_BS);
    float* aa_s  = (float*)(smem + SMEM_AA);
    float* bb_s  = (float*)(smem + SMEM_BB);

    const int tid  = threadIdx.x;
    const int lane = tid & 31;
    const int wid  = tid >> 5;    // 0..3
    const int gid  = lane >> 2;   // 0..7
    const int tig  = lane & 3;    // 0..3
    const int wy   = wid >> 1;    // 0..1  -> i
    const int wx   = wid & 1;     // 0..1  -> j
    const int i_w  = wy * 64;
    const int j_w  = wx * 64;

    const int b  = blockIdx.z;
    const int i0 = blockIdx.y * TILE;
    const int j0 = blockIdx.x * TILE;

    const float* Ab = A  + (size_t)b * C_DIM * NN;
    const float* Bb = Bm + (size_t)b * C_DIM * NN;

    // norms into smem (128 threads: each loads one aa and one bb)
    aa_s[tid] = g_aa[b * NN + i0 + tid];
    bb_s[tid] = g_bb[b * NN + j0 + tid];

    // Load tiles: gmem [c][n] -> smem [k=c][n], tf32-converted.
    // 2048 float4 per tile; 128 threads -> 16 iterations (both tiles per iter).
#pragma unroll
    for (int it = 0; it < 16; it++) {
        int t4   = tid + it * NTHREADS;      // float4 index 0..2047
        int c    = t4 >> 5;
        int col4 = (t4 & 31) << 2;
        float4 va = *(const float4*)&Ab[(size_t)c * NN + i0 + col4];
        float4 vb = *(const float4*)&Bb[(size_t)c * NN + j0 + col4];
        uint4 ua = { f2tf32(va.x), f2tf32(va.y), f2tf32(va.z), f2tf32(va.w) };
        uint4 ub = { f2tf32(vb.x), f2tf32(vb.y), f2tf32(vb.z), f2tf32(vb.w) };
        *(uint4*)&As[c * LDT + col4] = ua;
        *(uint4*)&Bs[c * LDT + col4] = ub;
    }
    __syncthreads();

    // accumulate: 4 m-tiles x 8 n-tiles of m16n8k8, over 8 k-steps
    float acc[4][8][4];
#pragma unroll
    for (int mt = 0; mt < 4; mt++)
#pragma unroll
        for (int nt = 0; nt < 8; nt++)
#pragma unroll
            for (int e = 0; e < 4; e++) acc[mt][nt][e] = 0.0f;

#pragma unroll
    for (int s = 0; s < 8; s++) {
        const int k0 = s * 8;
        uint32_t afr[4][4];
#pragma unroll
        for (int mt = 0; mt < 4; mt++) {
            int ib = i_w + mt * 16 + gid;
            afr[mt][0] = As[(k0 + tig)     * LDT + ib];
            afr[mt][1] = As[(k0 + tig)     * LDT + ib + 8];
            afr[mt][2] = As[(k0 + 4 + tig) * LDT + ib];
            afr[mt][3] = As[(k0 + 4 + tig) * LDT + ib + 8];
        }
        uint32_t bfr[8][2];
#pragma unroll
        for (int nt = 0; nt < 8; nt++) {
            int jb = j_w + nt * 8 + gid;
            bfr[nt][0] = Bs[(k0 + tig)     * LDT + jb];
            bfr[nt][1] = Bs[(k0 + 4 + tig) * LDT + jb];
        }
#pragma unroll
        for (int mt = 0; mt < 4; mt++)
#pragma unroll
            for (int nt = 0; nt < 8; nt++)
                mma_tf32(acc[mt][nt], afr[mt], bfr[nt]);
    }

    // epilogue: d = aa + bb - 2*ab, coalesced float2 stores (cols = j)
    float aav[4][2];
#pragma unroll
    for (int mt = 0; mt < 4; mt++) {
        aav[mt][0] = aa_s[i_w + mt * 16 + gid];
        aav[mt][1] = aa_s[i_w + mt * 16 + 8 + gid];
    }
    float bbv[8][2];
#pragma unroll
    for (int nt = 0; nt < 8; nt++) {
        bbv[nt][0] = bb_s[j_w + nt * 8 + 2 * tig];
        bbv[nt][1] = bb_s[j_w + nt * 8 + 2 * tig + 1];
    }

    float* Dbase = D + (size_t)b * NN * NN;
#pragma unroll
    for (int mt = 0; mt < 4; mt++) {
        int row0 = i0 + i_w + mt * 16 + gid;
#pragma unroll
        for (int nt = 0; nt < 8; nt++) {
            int col = j0 + j_w + nt * 8 + 2 * tig;
            float2 o0, o1;
            o0.x = aav[mt][0] + bbv[nt][0] - 2.0f * acc[mt][nt][0];
            o0.y = aav[mt][0] + bbv[nt][1] - 2.0f * acc[mt][nt][1];
            o1.x = aav[mt][1] + bbv[nt][0] - 2.0f * acc[mt][nt][2];
            o1.y = aav[mt][1] + bbv[nt][1] - 2.0f * acc[mt][nt][3];
            *(float2*)&Dbase[(size_t)row0 * NN + col]       = o0;
            *(float2*)&Dbase[(size_t)(row0 + 8) * NN + col] = o1;
        }
    }
}

// ---------------- launch ----------------

extern "C" void kernel_launch(void* const* d_in, const int* in_sizes, int n_in,
                              void* d_out, int out_size)
{
    const float* a = (const float*)d_in[0];
    const float* b = (const float*)d_in[1];
    float* out = (float*)d_out;

    cudaFuncSetAttribute(distmap_mma_kernel,
                         cudaFuncAttributeMaxDynamicSharedMemorySize, SMEM_TOTAL);

    norms_kernel<<<128, 256>>>(a, b);
    dim3 grid(NN / TILE, NN / TILE, 4);   // (32, 32, 4)
    distmap_mma_kernel<<<grid, NTHREADS, SMEM_TOTAL>>>(a, b, out);
}

// round 5
// speedup vs baseline: 2.4440x; 1.0399x over previous
#include <cuda_runtime.h>
#include <cstdint>

// DistMap: d[b,i,j] = aa[b,i] + bb[b,j] - 2 * sum_c a[b,c,i]*b[b,c,j]
// a: [B=4, C=64, N=4096] fp32, b: [4, 64, 4096] fp32, out: [4, 4096, 4096] fp32
// tf32 mma.sync m16n8k8, CTA 128x128, 4 warps (64x64), K=64 smem-resident.
// Logical-n permutation: within each warp's 64-j range,
//   j_local = 16*(nt>>1) + 4*tig + 2*(nt&1) + e
// so the epilogue stores one float4 per thread per group (coalesced 64B/line).

#define C_DIM 64
#define NN    4096
#define TILE  128
#define NTHREADS 128
#define LDT   132   // smem row stride (128 + 4 pad): conflict-free fragment LDS

// ---------------- norms precompute (exact fp32) ----------------

__device__ float g_aa[4 * NN];
__device__ float g_bb[4 * NN];

__global__ void norms_kernel(const float* __restrict__ A, const float* __restrict__ B) {
    int idx = blockIdx.x * blockDim.x + threadIdx.x;    // 0..32767
    int which = idx >> 14;
    int r = idx & 16383;                                 // b*4096 + i
    const float* src = (which ? B : A) + (size_t)(r >> 12) * (C_DIM * NN) + (r & 4095);
    float s = 0.0f;
#pragma unroll
    for (int c = 0; c < C_DIM; c++) { float v = src[(size_t)c * NN]; s += v * v; }
    (which ? g_bb : g_aa)[r] = s;
}

// ---------------- helpers ----------------

__device__ __forceinline__ uint32_t f2tf32(float x) {
    uint32_t u;
    asm("cvt.rna.tf32.f32 %0, %1;" : "=r"(u) : "f"(x));
    return u;
}

__device__ __forceinline__ void mma_tf32(float c[4], const uint32_t a[4], const uint32_t b[2]) {
    asm volatile(
        "mma.sync.aligned.m16n8k8.row.col.f32.tf32.tf32.f32 "
        "{%0,%1,%2,%3}, {%4,%5,%6,%7}, {%8,%9}, {%0,%1,%2,%3};"
        : "+f"(c[0]), "+f"(c[1]), "+f"(c[2]), "+f"(c[3])
        : "r"(a[0]), "r"(a[1]), "r"(a[2]), "r"(a[3]), "r"(b[0]), "r"(b[1]));
}

// ---------------- main kernel ----------------
// SMEM: As[64][LDT] ([k][i], tf32 bits), Bs[64][LDT] ([k][logical n]), aa_s, bb_s

#define SMEM_AS 0
#define SMEM_BS (64 * LDT * 4)
#define SMEM_AA (2 * 64 * LDT * 4)
#define SMEM_BB (SMEM_AA + 128 * 4)
#define SMEM_TOTAL (SMEM_BB + 128 * 4)

__global__ __launch_bounds__(NTHREADS, 2)
void distmap_mma_kernel(const float* __restrict__ A,   // [4, 64, 4096]
                        const float* __restrict__ Bm,  // [4, 64, 4096]
                        float* __restrict__ D)         // [4, 4096, 4096]
{
    extern __shared__ __align__(16) char smem[];
    uint32_t* As = (uint32_t*)(smem + SMEM_AS);
    uint32_t* Bs = (uint32_t*)(smem + SMEM_BS);
    float* aa_s  = (float*)(smem + SMEM_AA);
    float* bb_s  = (float*)(smem + SMEM_BB);

    const int tid  = threadIdx.x;
    const int lane = tid & 31;
    const int wid  = tid >> 5;    // 0..3
    const int gid  = lane >> 2;   // 0..7
    const int tig  = lane & 3;    // 0..3
    const int wy   = wid >> 1;    // 0..1  -> i
    const int wx   = wid & 1;     // 0..1  -> j
    const int i_w  = wy * 64;
    const int j_w  = wx * 64;

    const int b  = blockIdx.z;
    const int i0 = blockIdx.y * TILE;
    const int j0 = blockIdx.x * TILE;

    const float* Ab = A  + (size_t)b * C_DIM * NN;
    const float* Bb = Bm + (size_t)b * C_DIM * NN;

    // norms into smem (indexed by gmem i / j)
    aa_s[tid] = g_aa[b * NN + i0 + tid];
    bb_s[tid] = g_bb[b * NN + j0 + tid];

    // Load tiles. A: smem col = i_local (identity). B: smem col = logical n.
    // Gmem j_local -> logical n: with jj = j_local & 63, h = j_local >> 6:
    //   hh=(jj>>4)&3, t=(jj>>2)&3, p=(jj>>1)&1, e=jj&1
    //   n = 64*h + (2*hh + p)*8 + 2*t + e
    // A float4 at 4-aligned j maps to two float2 at n_base and n_base+8.
#pragma unroll
    for (int it = 0; it < 16; it++) {
        int t4   = tid + it * NTHREADS;      // float4 index 0..2047
        int c    = t4 >> 5;
        int col4 = (t4 & 31) << 2;
        float4 va = *(const float4*)&Ab[(size_t)c * NN + i0 + col4];
        float4 vb = *(const float4*)&Bb[(size_t)c * NN + j0 + col4];
        uint4 ua = { f2tf32(va.x), f2tf32(va.y), f2tf32(va.z), f2tf32(va.w) };
        *(uint4*)&As[c * LDT + col4] = ua;
        // B permuted scatter: e2 in {0,1} -> n_base+{0,1}; e2 in {2,3} -> n_base+8+{0,1}
        int h     = col4 >> 6;
        int hh    = (col4 >> 4) & 3;
        int t     = (col4 >> 2) & 3;
        int nbase = 64 * h + 16 * hh + 2 * t;
        uint2 lo = { f2tf32(vb.x), f2tf32(vb.y) };
        uint2 hi = { f2tf32(vb.z), f2tf32(vb.w) };
        *(uint2*)&Bs[c * LDT + nbase]     = lo;
        *(uint2*)&Bs[c * LDT + nbase + 8] = hi;
    }
    __syncthreads();

    // accumulate: 4 m-tiles x 8 n-tiles of m16n8k8, over 8 k-steps
    float acc[4][8][4];
#pragma unroll
    for (int mt = 0; mt < 4; mt++)
#pragma unroll
        for (int nt = 0; nt < 8; nt++)
#pragma unroll
            for (int e = 0; e < 4; e++) acc[mt][nt][e] = 0.0f;

#pragma unroll
    for (int s = 0; s < 8; s++) {
        const int k0 = s * 8;
        uint32_t afr[4][4];
#pragma unroll
        for (int mt = 0; mt < 4; mt++) {
            int ib = i_w + mt * 16 + gid;
            afr[mt][0] = As[(k0 + tig)     * LDT + ib];
            afr[mt][1] = As[(k0 + tig)     * LDT + ib + 8];
            afr[mt][2] = As[(k0 + 4 + tig) * LDT + ib];
            afr[mt][3] = As[(k0 + 4 + tig) * LDT + ib + 8];
        }
        uint32_t bfr[8][2];
#pragma unroll
        for (int nt = 0; nt < 8; nt++) {
            int jb = j_w + nt * 8 + gid;   // logical n (storage is logical-n indexed)
            bfr[nt][0] = Bs[(k0 + tig)     * LDT + jb];
            bfr[nt][1] = Bs[(k0 + 4 + tig) * LDT + jb];
        }
#pragma unroll
        for (int mt = 0; mt < 4; mt++)
#pragma unroll
            for (int nt = 0; nt < 8; nt++)
                mma_tf32(acc[mt][nt], afr[mt], bfr[nt]);
    }

    // epilogue: thread's float4 at gmem j_local = j_w + np*16 + 4*tig covers
    //   (nt=2np, e=0), (2np, 1), (2np+1, 0), (2np+1, 1)
    float4 bbv[4];
#pragma unroll
    for (int np = 0; np < 4; np++)
        bbv[np] = *(const float4*)&bb_s[j_w + np * 16 + 4 * tig];

    float aav[4][2];
#pragma unroll
    for (int mt = 0; mt < 4; mt++) {
        aav[mt][0] = aa_s[i_w + mt * 16 + gid];
        aav[mt][1] = aa_s[i_w + mt * 16 + 8 + gid];
    }

    float* Dbase = D + (size_t)b * NN * NN;
#pragma unroll
    for (int mt = 0; mt < 4; mt++) {
#pragma unroll
        for (int rh = 0; rh < 2; rh++) {
            int row = i0 + i_w + mt * 16 + rh * 8 + gid;
            float aa = aav[mt][rh];
            float* Drow = &Dbase[(size_t)row * NN + j0 + j_w + 4 * tig];
#pragma unroll
            for (int np = 0; np < 4; np++) {
                float4 o;
                o.x = aa + bbv[np].x - 2.0f * acc[mt][2 * np][rh * 2 + 0];
                o.y = aa + bbv[np].y - 2.0f * acc[mt][2 * np][rh * 2 + 1];
                o.z = aa + bbv[np].z - 2.0f * acc[mt][2 * np + 1][rh * 2 + 0];
                o.w = aa + bbv[np].w - 2.0f * acc[mt][2 * np + 1][rh * 2 + 1];
                *(float4*)&Drow[np * 16] = o;
            }
        }
    }
}

// ---------------- launch ----------------

extern "C" void kernel_launch(void* const* d_in, const int* in_sizes, int n_in,
                              void* d_out, int out_size)
{
    const float* a = (const float*)d_in[0];
    const float* b = (const float*)d_in[1];
    float* out = (float*)d_out;

    cudaFuncSetAttribute(distmap_mma_kernel,
                         cudaFuncAttributeMaxDynamicSharedMemorySize, SMEM_TOTAL);

    norms_kernel<<<128, 256>>>(a, b);
    dim3 grid(NN / TILE, NN / TILE, 4);   // (32, 32, 4)
    distmap_mma_kernel<<<grid, NTHREADS, SMEM_TOTAL>>>(a, b, out);
}